// round 5
// baseline (speedup 1.0000x reference)
#include <cuda_runtime.h>

// SPD log-map: for each 64x64 SPD matrix A, compute logm(A) = U diag(log w) U^T
// and emit the row-major upper triangle (2080 floats).
//
// Method: one-sided Jacobi on B := A. At convergence, columns of B are
// orthogonal with norms^2 = lambda_k^2, and
//   logm(A) = B diag(log(l_k)/l_k^2) B^T.
// No eigenvector accumulation needed. Sweeps are adaptive: stop after a
// "quiet" sweep (no rotation above 3e-6 relative orthogonality).

#define MDIM 64
#define LD   65          // smem column stride (odd -> conflict-free row reads)
#define MAXSWEEP 24
#define NTRI 2080        // 64*65/2

__global__ __launch_bounds__(1024)
void spd_log_kernel(const float* __restrict__ in, float* __restrict__ out)
{
    __shared__ float Bs[MDIM * LD];
    __shared__ float dv[MDIM];
    __shared__ int   nsig;

    const int tid  = threadIdx.x;
    const int warp = tid >> 5;
    const int lane = tid & 31;

    const float* A = in  + (size_t)blockIdx.x * (MDIM * MDIM);
    float*       O = out + (size_t)blockIdx.x * NTRI;

    // Load A (symmetric) into column-major smem: Bs[c*LD + r] = A[r*64 + c].
    for (int e = tid; e < MDIM * MDIM; e += 1024) {
        int r = e >> 6, c = e & 63;
        Bs[c * LD + r] = A[e];
    }
    if (tid == 0) nsig = 0;
    __syncthreads();

    // ---- One-sided Jacobi sweeps (adaptive) ----
    for (int sw = 0; sw < MAXSWEEP; sw++) {
        for (int rr = 0; rr < 63; rr++) {
            // Round-robin pairing: 32 disjoint pairs, warp w -> pair w.
            int p, q;
            if (warp == 0) {
                p = 63; q = rr;
            } else {
                p = rr + warp;       if (p >= 63) p -= 63;
                q = rr + 63 - warp;  if (q >= 63) q -= 63;
            }

            const int pb = p * LD, qb = q * LD;
            float bp0 = Bs[pb + lane],      bp1 = Bs[pb + 32 + lane];
            float bq0 = Bs[qb + lane],      bq1 = Bs[qb + 32 + lane];

            float app = bp0 * bp0 + bp1 * bp1;
            float aqq = bq0 * bq0 + bq1 * bq1;
            float apq = bp0 * bq0 + bp1 * bq1;

            #pragma unroll
            for (int o = 16; o; o >>= 1) {
                app += __shfl_xor_sync(0xffffffffu, app, o);
                aqq += __shfl_xor_sync(0xffffffffu, aqq, o);
                apq += __shfl_xor_sync(0xffffffffu, apq, o);
            }

            float a2 = apq * apq, pr = app * aqq;
            // Rotate down to ~1e-7 relative orthogonality.
            if (a2 > 1e-14f * pr) {
                // Significant (non-quiet) if above 3e-6 relative.
                if (a2 > 1e-11f * pr && lane == 0) nsig = 1;

                float th = (aqq - app) / (2.0f * apq);
                float t  = copysignf(1.0f, th) / (fabsf(th) + sqrtf(1.0f + th * th));
                float c  = rsqrtf(1.0f + t * t);
                float s  = t * c;

                Bs[pb + lane]      = c * bp0 - s * bq0;
                Bs[pb + 32 + lane] = c * bp1 - s * bq1;
                Bs[qb + lane]      = s * bp0 + c * bq0;
                Bs[qb + 32 + lane] = s * bp1 + c * bq1;
            }
            __syncthreads();
        }

        // Sweep-end: check quiet flag, reset for next sweep.
        int s = nsig;
        __syncthreads();                 // all threads read nsig before reset
        if (tid == 0) nsig = 0;
        __syncthreads();
        if (s == 0) break;               // quiet sweep -> converged
    }

    // ---- Column norms -> d_k = log(l_k)/l_k^2 = 0.5*log(n2)/n2, n2 = l^2 ----
    {
        int k = warp;
        #pragma unroll
        for (int h = 0; h < 2; h++, k += 32) {
            float x0 = Bs[k * LD + lane], x1 = Bs[k * LD + 32 + lane];
            float n2 = x0 * x0 + x1 * x1;
            #pragma unroll
            for (int o = 16; o; o >>= 1)
                n2 += __shfl_xor_sync(0xffffffffu, n2, o);
            if (lane == 0)
                dv[k] = 0.5f * logf(n2) / n2;
        }
    }
    __syncthreads();

    // ---- Reconstruction: out[i][j] = sum_k dv[k] * B[i,k] * B[j,k], i<=j ----
    for (int e = tid; e < NTRI; e += 1024) {
        int i = (int)((129.0f - sqrtf(16641.0f - 8.0f * (float)e)) * 0.5f);
        while ((i + 1) * (129 - (i + 1)) / 2 <= e) i++;
        while (i * (129 - i) / 2 > e) i--;
        int j = e - i * (129 - i) / 2 + i;

        float acc = 0.0f;
        #pragma unroll
        for (int k = 0; k < MDIM; k++)
            acc += (dv[k] * Bs[k * LD + i]) * Bs[k * LD + j];
        O[e] = acc;
    }
}

extern "C" void kernel_launch(void* const* d_in, const int* in_sizes, int n_in,
                              void* d_out, int out_size)
{
    const float* A = (const float*)d_in[0];
    float* out = (float*)d_out;
    int batch = in_sizes[0] / (MDIM * MDIM);   // 8192
    spd_log_kernel<<<batch, 1024>>>(A, out);
}

// round 6
// speedup vs baseline: 1.5012x; 1.5012x over previous
#include <cuda_runtime.h>

// SPD log-map: for each 64x64 SPD matrix A, compute logm(A) = U diag(log w) U^T
// and emit the row-major upper triangle (2080 floats).
//
// One-sided Jacobi on B := A; at convergence columns are orthogonal with
// norms = eigenvalues, and logm(A) = B diag(log(l)/l^2) B^T.
// Column norms are cached in smem and updated analytically per rotation
// (app' = app - t*apq, aqq' = aqq + t*apq), so each round needs only ONE
// 5-shfl butterfly (apq) instead of three. Norms are recomputed exactly at
// each sweep start to bound drift.

#define MDIM 64
#define LD   65          // smem column stride (odd -> conflict-free row reads)
#define MAXSWEEP 24
#define NTRI 2080        // 64*65/2
#define RTOL 1e-13f      // rotate if apq^2 > RTOL*app*aqq  (~3e-7 relative)
#define QTOL 1e-9f       // sweep "significant" above this   (~3e-5 relative)

__global__ __launch_bounds__(1024, 2)
void spd_log_kernel(const float* __restrict__ in, float* __restrict__ out)
{
    __shared__ float Bs[MDIM * LD];
    __shared__ float cn[MDIM];      // cached squared column norms
    __shared__ float dv[MDIM];
    __shared__ int   nsig;

    const int tid  = threadIdx.x;
    const int warp = tid >> 5;
    const int lane = tid & 31;

    const float* A = in  + (size_t)blockIdx.x * (MDIM * MDIM);
    float*       O = out + (size_t)blockIdx.x * NTRI;

    // Load A (symmetric) column-major: Bs[c*LD + r] = A[r*64 + c].
    for (int e = tid; e < MDIM * MDIM; e += 1024) {
        int r = e >> 6, c = e & 63;
        Bs[c * LD + r] = A[e];
    }
    if (tid == 0) nsig = 0;
    __syncthreads();

    // ---- One-sided Jacobi sweeps (adaptive) ----
    for (int sw = 0; sw < MAXSWEEP; sw++) {
        // Recompute exact column norms at sweep start (warp w -> cols w, w+32).
        #pragma unroll
        for (int h = 0; h < 2; h++) {
            int k = warp + 32 * h;
            float x0 = Bs[k * LD + lane], x1 = Bs[k * LD + 32 + lane];
            float n2 = x0 * x0 + x1 * x1;
            #pragma unroll
            for (int o = 16; o; o >>= 1)
                n2 += __shfl_xor_sync(0xffffffffu, n2, o);
            if (lane == 0) cn[k] = n2;
        }
        __syncthreads();

        for (int rr = 0; rr < 63; rr++) {
            // Round-robin pairing: 32 disjoint pairs, warp w -> pair w.
            int p, q;
            if (warp == 0) {
                p = 63; q = rr;
            } else {
                p = rr + warp;       if (p >= 63) p -= 63;
                q = rr + 63 - warp;  if (q >= 63) q -= 63;
            }

            const int pb = p * LD, qb = q * LD;
            float app = cn[p], aqq = cn[q];           // broadcast LDS
            float bp0 = Bs[pb + lane],      bp1 = Bs[pb + 32 + lane];
            float bq0 = Bs[qb + lane],      bq1 = Bs[qb + 32 + lane];

            float apq = bp0 * bq0 + bp1 * bq1;
            #pragma unroll
            for (int o = 16; o; o >>= 1)
                apq += __shfl_xor_sync(0xffffffffu, apq, o);

            float a2 = apq * apq, pr = app * aqq;
            if (a2 > RTOL * pr) {
                float th = (aqq - app) / (2.0f * apq);
                float t  = copysignf(1.0f, th) / (fabsf(th) + sqrtf(1.0f + th * th));
                float c  = rsqrtf(1.0f + t * t);
                float s  = t * c;

                Bs[pb + lane]      = c * bp0 - s * bq0;
                Bs[pb + 32 + lane] = c * bp1 - s * bq1;
                Bs[qb + lane]      = s * bp0 + c * bq0;
                Bs[qb + 32 + lane] = s * bp1 + c * bq1;

                if (lane == 0) {
                    cn[p] = app - t * apq;
                    cn[q] = aqq + t * apq;
                    if (a2 > QTOL * pr) nsig = 1;
                }
            }
            __syncthreads();
        }

        // Sweep-end: quiet check + reset.
        int s = nsig;
        __syncthreads();
        if (tid == 0) nsig = 0;
        __syncthreads();
        if (s == 0) break;
    }

    // ---- Exact column norms -> d_k = 0.5*log(n2)/n2  (n2 = lambda^2) ----
    #pragma unroll
    for (int h = 0; h < 2; h++) {
        int k = warp + 32 * h;
        float x0 = Bs[k * LD + lane], x1 = Bs[k * LD + 32 + lane];
        float n2 = x0 * x0 + x1 * x1;
        #pragma unroll
        for (int o = 16; o; o >>= 1)
            n2 += __shfl_xor_sync(0xffffffffu, n2, o);
        if (lane == 0) dv[k] = 0.5f * logf(n2) / n2;
    }
    __syncthreads();

    // ---- Reconstruction: out[i][j] = sum_k dv[k]*B[i,k]*B[j,k], i<=j ----
    // Warp w owns rows w and 63-w (balanced: 64-i elements in row i).
    #pragma unroll
    for (int rsel = 0; rsel < 2; rsel++) {
        int i = rsel ? (63 - warp) : warp;
        int base = i * (129 - i) / 2;               // row offset in triangle
        for (int j = i + lane; j < MDIM; j += 32) {
            float acc = 0.0f;
            #pragma unroll
            for (int k = 0; k < MDIM; k++)
                acc += (dv[k] * Bs[k * LD + i]) * Bs[k * LD + j];
            O[base + (j - i)] = acc;
        }
    }
}

extern "C" void kernel_launch(void* const* d_in, const int* in_sizes, int n_in,
                              void* d_out, int out_size)
{
    const float* A = (const float*)d_in[0];
    float* out = (float*)d_out;
    int batch = in_sizes[0] / (MDIM * MDIM);   // 8192
    spd_log_kernel<<<batch, 1024>>>(A, out);
}

// round 8
// speedup vs baseline: 1.6382x; 1.0913x over previous
#include <cuda_runtime.h>

// SPD log-map: for each 64x64 SPD matrix A, compute logm(A) = U diag(log w) U^T
// and emit the row-major upper triangle (2080 floats).
//
// One-sided Jacobi on B := A; at convergence columns are orthogonal with
// norms = eigenvalues, and logm(A) = B diag(log(l)/l^2) B^T.
//  - float2 column layout (stride 33 float2): half the LDS/STS per round
//  - cached column norms updated analytically per rotation
//  - incremental round-robin index bookkeeping
//  - shfl butterfly reduction (redux.f32 unsupported by this ptxas target)

#define MDIM 64
#define LD2  33          // float2 stride per column (odd -> conflict-free)
#define LDF  66          // same stride in floats
#define MAXSWEEP 24
#define NTRI 2080
#define RTOL 1e-13f      // rotate above ~3e-7 relative orthogonality
#define QTOL 1e-8f       // sweep "significant" above ~1e-4 relative

__device__ __forceinline__ float warp_sum(float v) {
    #pragma unroll
    for (int o = 16; o; o >>= 1)
        v += __shfl_xor_sync(0xffffffffu, v, o);
    return v;
}

__global__ __launch_bounds__(1024, 2)
void spd_log_kernel(const float* __restrict__ in, float* __restrict__ out)
{
    __shared__ float2 Bs[MDIM * LD2];   // column c: float2 j = rows (2j, 2j+1)
    __shared__ float  Cs[MDIM * LDF];   // dv-scaled copy for reconstruction
    __shared__ float  cn[MDIM];
    __shared__ float  dv[MDIM];
    __shared__ int    nsig;

    const int tid  = threadIdx.x;
    const int warp = tid >> 5;
    const int lane = tid & 31;

    float* Bf = (float*)Bs;             // B[r, c] == Bf[c*LDF + r]

    const float* A = in  + (size_t)blockIdx.x * (MDIM * MDIM);
    float*       O = out + (size_t)blockIdx.x * NTRI;

    // Load (A symmetric): Bf[c*LDF + r] = A[c*64 + r]; contiguous both sides.
    for (int e = tid; e < MDIM * MDIM; e += 1024) {
        int c = e >> 6, r = e & 63;
        Bf[c * LDF + r] = A[e];
    }
    if (tid == 0) nsig = 0;
    __syncthreads();

    // ---- One-sided Jacobi sweeps (adaptive) ----
    for (int sw = 0; sw < MAXSWEEP; sw++) {
        // Exact column norms at sweep start: warp w -> cols w, w+32.
        #pragma unroll
        for (int h = 0; h < 2; h++) {
            int k = warp + 32 * h;
            float2 x = Bs[k * LD2 + lane];
            float n2 = warp_sum(fmaf(x.x, x.x, x.y * x.y));
            if (lane == 0) cn[k] = n2;
        }
        __syncthreads();

        // Incremental round-robin: p,q both step +1 mod 63 (warp0: p=63 fixed).
        int p = (warp == 0) ? 63 : warp;
        int q = (warp == 0) ? 0  : 63 - warp;

        for (int rr = 0; rr < 63; rr++) {
            const int pb = p * LD2 + lane, qb = q * LD2 + lane;
            float app = cn[p], aqq = cn[q];
            float2 bp = Bs[pb];
            float2 bq = Bs[qb];

            float apq = warp_sum(fmaf(bp.x, bq.x, bp.y * bq.y));

            float a2 = apq * apq, pr = app * aqq;
            if (a2 > RTOL * pr) {
                float th = (aqq - app) / (2.0f * apq);
                float t  = copysignf(1.0f, th) / (fabsf(th) + sqrtf(1.0f + th * th));
                float c  = rsqrtf(1.0f + t * t);
                float s  = t * c;

                Bs[pb] = make_float2(c * bp.x - s * bq.x, c * bp.y - s * bq.y);
                Bs[qb] = make_float2(s * bp.x + c * bq.x, s * bp.y + c * bq.y);

                if (lane == 0) {
                    cn[p] = app - t * apq;
                    cn[q] = aqq + t * apq;
                    if (a2 > QTOL * pr) nsig = 1;
                }
            }
            __syncthreads();

            if (warp) { p++; if (p == 63) p = 0; }
            q++; if (q == 63) q = 0;
        }

        int s = nsig;
        __syncthreads();
        if (tid == 0) nsig = 0;
        __syncthreads();
        if (s == 0) break;
    }

    // ---- dv_k = log(l_k)/l_k^2 = 0.5*log(n2)/n2, n2 = l^2 ----
    #pragma unroll
    for (int h = 0; h < 2; h++) {
        int k = warp + 32 * h;
        float2 x = Bs[k * LD2 + lane];
        float n2 = warp_sum(fmaf(x.x, x.x, x.y * x.y));
        if (lane == 0) dv[k] = 0.5f * logf(n2) / n2;
    }
    __syncthreads();

    // ---- Cs[k][r] = dv[k] * B[r,k] ----
    for (int e = tid; e < MDIM * MDIM; e += 1024) {
        int k = e >> 6, r = e & 63;
        Cs[k * LDF + r] = dv[k] * Bf[k * LDF + r];
    }
    __syncthreads();

    // ---- out[i][j] = sum_k Cs[k][i] * B[j,k], i<=j.  Warp w: rows w, 63-w ----
    #pragma unroll
    for (int rsel = 0; rsel < 2; rsel++) {
        int i = rsel ? (63 - warp) : warp;
        int base = i * (129 - i) / 2;
        for (int j = i + lane; j < MDIM; j += 32) {
            float acc = 0.0f;
            #pragma unroll
            for (int k = 0; k < MDIM; k++)
                acc += Cs[k * LDF + i] * Bf[k * LDF + j];
            O[base + (j - i)] = acc;
        }
    }
}

extern "C" void kernel_launch(void* const* d_in, const int* in_sizes, int n_in,
                              void* d_out, int out_size)
{
    const float* A = (const float*)d_in[0];
    float* out = (float*)d_out;
    int batch = in_sizes[0] / (MDIM * MDIM);   // 8192
    spd_log_kernel<<<batch, 1024>>>(A, out);
}

// round 9
// speedup vs baseline: 2.6962x; 1.6458x over previous
#include <cuda_runtime.h>

// SPD log-map: for each 64x64 SPD matrix A, compute logm(A) = U diag(log w) U^T
// and emit the row-major upper triangle (2080 floats).
//
// One-sided Jacobi on B := A; at convergence columns are orthogonal with
// norms = eigenvalues, and logm(A) = B diag(log(l)/l^2) B^T.
//  - 512 threads/CTA, 4 CTAs/SM; each 16-lane HALF-WARP owns one column pair
//    (2 pairs per warp -> ~0.65x warp-instruction stream in the sweep loop)
//  - float2 column layout (stride 33 float2, conflict-free)
//  - 4-shfl butterfly reduction within half-warps
//  - cached column norms updated analytically per rotation
//  - incremental round-robin index bookkeeping

#define MDIM 64
#define LD2  33          // float2 stride per column
#define LDF  66          // same stride in floats
#define MAXSWEEP 24
#define NTRI 2080
#define RTOL 1e-13f      // rotate above ~3e-7 relative orthogonality
#define QTOL 1e-8f       // sweep "significant" above ~1e-4 relative

__device__ __forceinline__ float half_sum(float v) {
    #pragma unroll
    for (int o = 8; o; o >>= 1)
        v += __shfl_xor_sync(0xffffffffu, v, o);
    return v;                 // sum within each 16-lane half-warp
}

__global__ __launch_bounds__(512, 4)
void spd_log_kernel(const float* __restrict__ in, float* __restrict__ out)
{
    __shared__ float2 Bs[MDIM * LD2];   // column c: float2 j = rows (2j,2j+1)
    __shared__ float  Cs[MDIM * LDF];   // dv-scaled copy for reconstruction
    __shared__ float  cn[MDIM];
    __shared__ float  dv[MDIM];
    __shared__ int    nsig;

    const int tid    = threadIdx.x;
    const int pairid = tid >> 4;        // 0..31: half-warp id
    const int hl     = tid & 15;        // lane within half-warp
    const int warp   = tid >> 5;        // 0..15
    const int lane   = tid & 31;

    float* Bf = (float*)Bs;             // B[r, c] == Bf[c*LDF + r]

    const float* A = in  + (size_t)blockIdx.x * (MDIM * MDIM);
    float*       O = out + (size_t)blockIdx.x * NTRI;

    // Load (A symmetric): Bf[c*LDF + r] = A[c*64 + r]; contiguous both sides.
    for (int e = tid; e < MDIM * MDIM; e += 512) {
        int c = e >> 6, r = e & 63;
        Bf[c * LDF + r] = A[e];
    }
    if (tid == 0) nsig = 0;
    __syncthreads();

    // ---- One-sided Jacobi sweeps (adaptive) ----
    for (int sw = 0; sw < MAXSWEEP; sw++) {
        // Exact column norms at sweep start: half-warp h -> cols h, h+32.
        #pragma unroll
        for (int h = 0; h < 2; h++) {
            int k = pairid + 32 * h;
            float2 x0 = Bs[k * LD2 + hl];
            float2 x1 = Bs[k * LD2 + 16 + hl];
            float n2 = half_sum(fmaf(x0.x, x0.x, x0.y * x0.y) +
                                fmaf(x1.x, x1.x, x1.y * x1.y));
            if (hl == 0) cn[k] = n2;
        }
        __syncthreads();

        // Incremental round-robin: p,q step +1 mod 63 (pair 0: p=63 fixed).
        int p = (pairid == 0) ? 63 : pairid;
        int q = (pairid == 0) ? 0  : 63 - pairid;

        for (int rr = 0; rr < 63; rr++) {
            const int pb = p * LD2 + hl, qb = q * LD2 + hl;
            float app = cn[p], aqq = cn[q];
            float2 bp0 = Bs[pb],      bq0 = Bs[qb];
            float2 bp1 = Bs[pb + 16], bq1 = Bs[qb + 16];

            float apq = half_sum(fmaf(bp0.x, bq0.x, bp0.y * bq0.y) +
                                 fmaf(bp1.x, bq1.x, bp1.y * bq1.y));

            float a2 = apq * apq, pr = app * aqq;
            bool rot = a2 > RTOL * pr;              // uniform per half-warp
            if (__any_sync(0xffffffffu, rot)) {
                float th = (aqq - app) / (2.0f * apq);
                float t  = copysignf(1.0f, th) / (fabsf(th) + sqrtf(1.0f + th * th));
                float c  = rsqrtf(1.0f + t * t);
                float s  = t * c;

                if (rot) {
                    Bs[pb]      = make_float2(c * bp0.x - s * bq0.x, c * bp0.y - s * bq0.y);
                    Bs[pb + 16] = make_float2(c * bp1.x - s * bq1.x, c * bp1.y - s * bq1.y);
                    Bs[qb]      = make_float2(s * bp0.x + c * bq0.x, s * bp0.y + c * bq0.y);
                    Bs[qb + 16] = make_float2(s * bp1.x + c * bq1.x, s * bp1.y + c * bq1.y);
                    if (hl == 0) {
                        cn[p] = app - t * apq;
                        cn[q] = aqq + t * apq;
                        if (a2 > QTOL * pr) nsig = 1;
                    }
                }
            }
            __syncthreads();

            if (pairid) { p++; if (p == 63) p = 0; }
            q++; if (q == 63) q = 0;
        }

        int s = nsig;
        __syncthreads();
        if (tid == 0) nsig = 0;
        __syncthreads();
        if (s == 0) break;
    }

    // ---- dv_k = log(l_k)/l_k^2 = 0.5*log(n2)/n2, n2 = l^2 ----
    #pragma unroll
    for (int h = 0; h < 2; h++) {
        int k = pairid + 32 * h;
        float2 x0 = Bs[k * LD2 + hl];
        float2 x1 = Bs[k * LD2 + 16 + hl];
        float n2 = half_sum(fmaf(x0.x, x0.x, x0.y * x0.y) +
                            fmaf(x1.x, x1.x, x1.y * x1.y));
        if (hl == 0) dv[k] = 0.5f * logf(n2) / n2;
    }
    __syncthreads();

    // ---- Cs[k][r] = dv[k] * B[r,k] ----
    for (int e = tid; e < MDIM * MDIM; e += 512) {
        int k = e >> 6, r = e & 63;
        Cs[k * LDF + r] = dv[k] * Bf[k * LDF + r];
    }
    __syncthreads();

    // ---- out[i][j] = sum_k Cs[k][i]*B[j,k], i<=j.
    //      Warp w owns rows {w, 63-w, 16+w, 47-w}: 130 elements each. ----
    #pragma unroll
    for (int rsel = 0; rsel < 4; rsel++) {
        int i = (rsel == 0) ? warp
              : (rsel == 1) ? 63 - warp
              : (rsel == 2) ? 16 + warp
                            : 47 - warp;
        int base = i * (129 - i) / 2;
        for (int j = i + lane; j < MDIM; j += 32) {
            float acc = 0.0f;
            #pragma unroll
            for (int k = 0; k < MDIM; k++)
                acc += Cs[k * LDF + i] * Bf[k * LDF + j];
            O[base + (j - i)] = acc;
        }
    }
}

extern "C" void kernel_launch(void* const* d_in, const int* in_sizes, int n_in,
                              void* d_out, int out_size)
{
    const float* A = (const float*)d_in[0];
    float* out = (float*)d_out;
    int batch = in_sizes[0] / (MDIM * MDIM);   // 8192
    spd_log_kernel<<<batch, 512>>>(A, out);
}